// round 16
// baseline (speedup 1.0000x reference)
#include <cuda_runtime.h>

// ReduceBoundingBoxes: decode + threshold + stable sort + greedy NMS.
// ONE CLUSTER of 8 CTAs x 1024 threads. Hardware cluster barriers (~380cyc,
// release/acquire) replace global-atomic spin barriers; compaction counters
// live in CTA 0's SMEM (DSMEM atomics) -> zero persistent global control
// state, no per-replay resets.
//   init: CTA0 zeroes counters; all CTAs zero output
//   CS1
//   P0: decode + warp-aggregated DSMEM compaction (valid + active counts)
//   CS2
//   P1: stable rank via packed u64 keys, dual-key warps, packed (r,ra)
//   CS3  (CTAs != 0 exit)
//   P4: CTA 0: in-SMEM ballot suppression matrix + sparse scan + scatter

#define NCELL   9216
#define PDIM    96
#define WIDTHF  3072.0f
#define HEIGHTF 2304.0f
#define XPSF    32.0f    // multiplies ROW index (P dim)
#define YPSF    24.0f    // multiplies COL index (Q dim)
#define MAXNW   144      // ceil(9216/64)
#define NBLK    8
#define NTHR    1024
#define GTOT    (NBLK * NTHR)
#define NWARP   (NBLK * 32)       // 256 grid-wide P1 warps
#define DSMEM_BYTES 184320

typedef unsigned long long u64;

// -------- global scratch (static device memory; data only, no control) ------
__device__ float  g_cscore[NCELL];
__device__ float4 g_cbox[NCELL];
__device__ int    g_corig[NCELL];
__device__ unsigned char g_cact[NCELL];
__device__ float  g_sscore[NCELL];
__device__ float4 g_sbox[NCELL];
__device__ float4 g_abox[NCELL];    // active boxes in rank order
__device__ int    g_amap[NCELL];    // active a -> global sorted rank r
__device__ u64    g_sup[(size_t)NCELL * MAXNW];   // fallback only (A large)

extern __shared__ unsigned char dyn_smem[];

// ---- cluster helpers -------------------------------------------------------
__device__ __forceinline__ unsigned smem_u32(const void* p)
{
    unsigned r;
    asm("{ .reg .u64 t; cvta.to.shared.u64 t, %1; cvt.u32.u64 %0, t; }"
        : "=r"(r) : "l"(p));
    return r;
}
__device__ __forceinline__ unsigned cta_rank()
{
    unsigned r; asm("mov.u32 %0, %%cluster_ctarank;" : "=r"(r)); return r;
}
__device__ __forceinline__ void cluster_sync()
{
    asm volatile("barrier.cluster.arrive.aligned;" ::: "memory");
    asm volatile("barrier.cluster.wait.aligned;"   ::: "memory");
}
__device__ __forceinline__ unsigned map0(unsigned local_addr)
{
    unsigned rem;
    asm("mapa.shared::cluster.u32 %0, %1, %2;" : "=r"(rem)
        : "r"(local_addr), "r"(0u));
    return rem;
}
__device__ __forceinline__ unsigned dsm_atomic_add(unsigned rem_addr, unsigned v)
{
    unsigned old;
    asm volatile("atom.shared::cluster.add.u32 %0, [%1], %2;"
                 : "=r"(old) : "r"(rem_addr), "r"(v) : "memory");
    return old;
}
__device__ __forceinline__ unsigned dsm_load(unsigned rem_addr)
{
    unsigned v;
    asm volatile("ld.shared::cluster.u32 %0, [%1];" : "=r"(v) : "r"(rem_addr));
    return v;
}

__global__ __launch_bounds__(NTHR, 1) __cluster_dims__(NBLK, 1, 1)
void rbb_cluster(const float* __restrict__ x, float* __restrict__ out)
{
    const int tid  = threadIdx.x;
    const int bid  = (int)cta_rank();
    const int gtid = bid * NTHR + tid;
    const int wid  = tid >> 5;
    const int lane = tid & 31;

    __shared__ unsigned s_ctr[2];      // [0]=valid count, [1]=active (CTA0's)
    const unsigned ctr_rem = map0(smem_u32(s_ctr));

    if (bid == 0 && tid < 2) s_ctr[tid] = 0u;

    // zero output: 46080 floats = 11520 float4 across the cluster
    for (int i = gtid; i < 11520; i += GTOT)
        ((float4*)out)[i] = make_float4(0.f, 0.f, 0.f, 0.f);
    cluster_sync();                    // counters visible

    // ---------------- P0: decode + compact + act -----------------------------
    for (int c = gtid; c < NCELL; c += GTOT) {
        float s = x[c];
        bool valid = s > 0.9f;
        bool act = false;
        float bx1 = 0.f, by1 = 0.f, bx2 = 0.f, by2 = 0.f;
        if (valid) {
            int   p  = c / PDIM;
            int   q  = c - p * PDIM;
            float ii = (float)p * XPSF;
            float jj = (float)q * YPSF;
            float v1 = x[1 * NCELL + c];
            float v2 = x[2 * NCELL + c];
            float v3 = x[3 * NCELL + c];
            float v4 = x[4 * NCELL + c];
            bx1 = v1 * WIDTHF  + ii;
            by1 = v2 * HEIGHTF + jj;
            bx2 = (v3 - v1) * WIDTHF  + ii;
            by2 = (v4 - v2) * HEIGHTF + jj;
            act = (bx2 > bx1) && (by2 > by1);
        }
        unsigned vmask = __ballot_sync(0xFFFFFFFFu, valid);
        unsigned amask = __ballot_sync(0xFFFFFFFFu, act);
        if (vmask) {
            int leader = __ffs(vmask) - 1;
            unsigned base = 0;
            if (lane == leader) {
                base = dsm_atomic_add(ctr_rem, (unsigned)__popc(vmask));
                if (amask) dsm_atomic_add(ctr_rem + 4, (unsigned)__popc(amask));
            }
            base = __shfl_sync(0xFFFFFFFFu, base, leader);
            if (valid) {
                int k = (int)base + __popc(vmask & ((1u << lane) - 1u));
                g_cscore[k] = s;
                g_cbox[k]   = make_float4(bx1, by1, bx2, by2);
                g_corig[k]  = c;
                g_cact[k]   = act ? 1 : 0;
            }
        }
    }
    cluster_sync();                    // compaction visible (release+acquire)

    const int M = (int)dsm_load(ctr_rem);
    const int A = (int)dsm_load(ctr_rem + 4);

    // ---------------- P1: rank (global + active) via packed u64 keys ---------
    // key = (score_bits << 32) | ~orig: order-isomorphic, unique, nonzero.
    {
        u64*      skey  = (u64*)dyn_smem;                    // [M rounded to 32]
        unsigned* sactw = (unsigned*)(dyn_smem + 73728);     // [ceil(M/32)]

        const int nit = (M + 31) >> 5;
        const int M32 = nit << 5;

        for (int i = tid; i < M32; i += NTHR)
            skey[i] = (i < M)
                ? (((u64)__float_as_uint(g_cscore[i]) << 32)
                   | (u64)(0xFFFFFFFFu - (unsigned)g_corig[i]))
                : 0ull;
        for (int t = 0; t < M32; t += NTHR) {
            int i = t + tid;
            bool a = (i < M) && (g_cact[i] != 0);
            unsigned bal = __ballot_sync(0xFFFFFFFFu, a);
            if (lane == 0 && i < M32) sactw[i >> 5] = bal;
        }
        __syncthreads();

        // dual-key per warp; packed (r<<16)|ra single reduction per key
        for (int kk = bid * 32 + wid; kk < M; kk += 2 * NWARP) {
            const int kA = kk;
            const int kB = kk + NWARP;
            const bool hasB = (kB < M);
            u64 keyA = skey[kA];
            u64 keyB = hasB ? skey[kB] : ~0ull;
            int accA = 0, accB = 0;
            for (int it = 0; it < nit; it++) {
                u64 kj = skey[(it << 5) + lane];
                int w  = 0x10000 | (int)((sactw[it] >> lane) & 1u);
                if (kj > keyA) accA += w;
                if (kj > keyB) accB += w;
            }
            accA = __reduce_add_sync(0xFFFFFFFFu, accA);
            accB = __reduce_add_sync(0xFFFFFFFFu, accB);
            if (lane == 0) {
                {
                    int r = accA >> 16, ra = accA & 0xFFFF;
                    float4 bk = g_cbox[kA];
                    g_sbox[r]   = bk;
                    g_sscore[r] = g_cscore[kA];
                    if (g_cact[kA]) { g_abox[ra] = bk; g_amap[ra] = r; }
                }
                if (hasB) {
                    int r = accB >> 16, ra = accB & 0xFFFF;
                    float4 bk = g_cbox[kB];
                    g_sbox[r]   = bk;
                    g_sscore[r] = g_cscore[kB];
                    if (g_cact[kB]) { g_abox[ra] = bk; g_amap[ra] = r; }
                }
            }
        }
    }
    cluster_sync();                    // sorted arrays visible to CTA 0

    if (bid != 0) return;              // no cluster ops remain; safe to exit

    // ---------------- P4 (CTA 0): in-SMEM matrix + scan + scatter ------------
    {
        __shared__ u64 skeepA[MAXNW];
        __shared__ u64 skeepR[MAXNW];
        __shared__ u64 snz[MAXNW];

        const int na = (A + 63) >> 6;
        float4* sabox = (float4*)dyn_smem;
        int*    samap = (int*)(dyn_smem + (size_t)A * 16);
        size_t  supoff = ((size_t)A * 20 + 7) & ~(size_t)7;
        u64*    ssup  = (u64*)(dyn_smem + supoff);
        const bool fast = (supoff + (size_t)A * na * 8) <= DSMEM_BYTES;

        __syncthreads();               // skey region dead before overlay reuse
        for (int a = tid; a < A; a += NTHR) {
            sabox[a] = g_abox[a];
            samap[a] = g_amap[a];
        }
        if (tid < MAXNW) {
            snz[tid] = 0ull;
            if (tid < na) {
                int nb = A - (tid << 6);
                skeepA[tid] = (nb >= 64) ? ~0ull : ((1ull << nb) - 1ull);
            }
            int nwR = (M + 63) >> 6;
            if (tid < nwR) {
                int nb = M - (tid << 6);
                skeepR[tid] = (nb >= 64) ? ~0ull : ((1ull << nb) - 1ull);
            }
        }
        __syncthreads();

        // suppression bit-matrix via warp ballots; division-free predicate:
        // denom = ai+aj-inter+1e-9 > 0 => iou>0.5 <=> inter > 0.5*denom.
        for (int i = wid; i < A; i += 32) {
            float4 bi = sabox[i];
            float  ai = (bi.z - bi.x) * (bi.w - bi.y);
            u64 rowor = 0;
            for (int w = (i >> 6); w < na; w++) {
                int j1 = (w << 6) + lane;
                int j2 = j1 + 32;
                bool p1 = false, p2 = false;
                if (j1 > i && j1 < A) {
                    float4 bj = sabox[j1];
                    float  aj = (bj.z - bj.x) * (bj.w - bj.y);
                    float iw = fmaxf(fminf(bi.z, bj.z) - fmaxf(bi.x, bj.x), 0.0f);
                    float ih = fmaxf(fminf(bi.w, bj.w) - fmaxf(bi.y, bj.y), 0.0f);
                    float inter = iw * ih;
                    p1 = inter > 0.5f * (ai + aj - inter + 1e-9f);
                }
                if (j2 > i && j2 < A) {
                    float4 bj = sabox[j2];
                    float  aj = (bj.z - bj.x) * (bj.w - bj.y);
                    float iw = fmaxf(fminf(bi.z, bj.z) - fmaxf(bi.x, bj.x), 0.0f);
                    float ih = fmaxf(fminf(bi.w, bj.w) - fmaxf(bi.y, bj.y), 0.0f);
                    float inter = iw * ih;
                    p2 = inter > 0.5f * (ai + aj - inter + 1e-9f);
                }
                unsigned lo = __ballot_sync(0xFFFFFFFFu, p1);
                unsigned hi = __ballot_sync(0xFFFFFFFFu, p2);
                u64 bits = (u64)lo | ((u64)hi << 32);
                if (lane == 0) {
                    if (fast) ssup[(size_t)i * na + w] = bits;
                    else      g_sup[(size_t)i * na + w] = bits;
                }
                rowor |= bits;
            }
            if (lane == 0 && rowor)
                atomicOr(&snz[i >> 6], 1ull << (i & 63));
        }
        __syncthreads();

        // sparse chunked greedy scan over actives
        if (tid < 32 && A > 0) {
            const int ln = tid;
            for (int c = 0; c < na; c++) {
                const int base = c << 6;

                if (ln == 0) {
                    u64 kw  = skeepA[c];
                    u64 rem = kw & snz[c];
                    while (rem) {
                        int b = __ffsll((long long)rem) - 1;
                        u64 s = fast ? ssup[(size_t)(base + b) * na + c]
                                     : g_sup[(size_t)(base + b) * na + c];
                        kw  &= ~s;          // bits in s are strictly > b
                        rem &= ~s;
                        rem &= rem - 1;     // clear processed (lowest) bit
                    }
                    skeepA[c] = kw;
                }
                __syncwarp();

                const u64 kwnz = skeepA[c] & snz[c];
                if (kwnz) {
                    for (int w = c + 1 + ln; w < na; w += 32) {
                        u64 acc = 0, t = kwnz;
                        while (t) {
                            int b = __ffsll((long long)t) - 1;
                            t &= t - 1;
                            acc |= fast ? ssup[(size_t)(base + b) * na + w]
                                        : g_sup[(size_t)(base + b) * na + w];
                        }
                        skeepA[w] &= ~acc;
                    }
                }
                __syncwarp();
            }
        }
        __syncthreads();

        // map suppressed actives back to global sorted ranks
        for (int a = tid; a < A; a += NTHR) {
            if (!((skeepA[a >> 6] >> (a & 63)) & 1ull)) {
                int r = samap[a];
                atomicAnd(&skeepR[r >> 6], ~(1ull << (r & 63)));
            }
        }
        __syncthreads();

        // scatter kept rows (output zeroed at start)
        for (int r = tid; r < M; r += NTHR) {
            if ((skeepR[r >> 6] >> (r & 63)) & 1ull) {
                float4 b = g_sbox[r];
                out[r * 5 + 0] = g_sscore[r];
                out[r * 5 + 1] = b.x;
                out[r * 5 + 2] = b.y;
                out[r * 5 + 3] = b.z - b.x;
                out[r * 5 + 4] = b.w - b.y;
            }
        }
    }
}

// ---------------------------------------------------------------------------
extern "C" void kernel_launch(void* const* d_in, const int* in_sizes, int n_in,
                              void* d_out, int out_size)
{
    (void)in_sizes; (void)n_in; (void)out_size;
    const float* x   = (const float*)d_in[0];
    float*       out = (float*)d_out;

    cudaFuncSetAttribute(rbb_cluster,
                         cudaFuncAttributeMaxDynamicSharedMemorySize,
                         DSMEM_BYTES);

    rbb_cluster<<<NBLK, NTHR, DSMEM_BYTES>>>(x, out);
}

// round 17
// speedup vs baseline: 1.7795x; 1.7795x over previous
#include <cuda_runtime.h>

// ReduceBoundingBoxes: decode + threshold + stable sort + greedy NMS.
// SINGLE persistent kernel, 18 blocks x 1024 threads (R14 structure).
//   P0: zero output, decode + warp-aggregated compaction, act flag + count
//   B1  (full spin barrier - everyone needs M)
//   P1: stable rank via packed u64 keys, dual-key warps, packed (r,ra)
//   arrive-only: blocks != 0 post one arrival and EXIT (no spin)
//   P4: block 0 (after spinning to 2*NBLK): in-SMEM ballot suppression
//       matrix + sparse chunked greedy scan + map back + scatter
//   end: block 0 (provably last) resets the 3 counters for the next replay.

#define NCELL   9216
#define PDIM    96
#define WIDTHF  3072.0f
#define HEIGHTF 2304.0f
#define XPSF    32.0f    // multiplies ROW index (P dim)
#define YPSF    24.0f    // multiplies COL index (Q dim)
#define MAXNW   144      // ceil(9216/64)
#define NBLK    18
#define NTHR    1024
#define GTOT    (NBLK * NTHR)
#define NWARP   (NBLK * 32)       // 576 grid-wide P1 warps
#define DSMEM_BYTES 184320

typedef unsigned long long u64;

// -------- global scratch (static device memory) ----------------------------
__device__ int    g_cnt;    // valid-box count;  reset by block 0 at end
__device__ int    g_acnt;   // active-box count; reset by block 0 at end
__device__ int    g_bar;    // barrier arrivals; reset by block 0 at end
__device__ float  g_cscore[NCELL];
__device__ float4 g_cbox[NCELL];
__device__ int    g_corig[NCELL];
__device__ unsigned char g_cact[NCELL];
__device__ float  g_sscore[NCELL];
__device__ float4 g_sbox[NCELL];
__device__ float4 g_abox[NCELL];    // active boxes in rank order
__device__ int    g_amap[NCELL];    // active a -> global sorted rank r
__device__ u64    g_sup[(size_t)NCELL * MAXNW];   // fallback only (A large)

extern __shared__ unsigned char dyn_smem[];

__global__ __launch_bounds__(NTHR, 1)
void rbb_fused(const float* __restrict__ x, float* __restrict__ out)
{
    const int tid  = threadIdx.x;
    const int bid  = blockIdx.x;
    const int gtid = bid * NTHR + tid;
    const int wid  = tid >> 5;
    const int lane = tid & 31;

    // ---------------- P0: zero output, decode + compact + act ----------------
    for (int i = gtid; i < (NCELL * 5) / 4; i += GTOT)
        ((float4*)out)[i] = make_float4(0.f, 0.f, 0.f, 0.f);

    for (int c = gtid; c < NCELL; c += GTOT) {
        float s = x[c];
        bool valid = s > 0.9f;
        bool act = false;
        float bx1 = 0.f, by1 = 0.f, bx2 = 0.f, by2 = 0.f;
        if (valid) {
            int   p  = c / PDIM;
            int   q  = c - p * PDIM;
            float ii = (float)p * XPSF;
            float jj = (float)q * YPSF;
            float v1 = x[1 * NCELL + c];
            float v2 = x[2 * NCELL + c];
            float v3 = x[3 * NCELL + c];
            float v4 = x[4 * NCELL + c];
            bx1 = v1 * WIDTHF  + ii;
            by1 = v2 * HEIGHTF + jj;
            bx2 = (v3 - v1) * WIDTHF  + ii;
            by2 = (v4 - v2) * HEIGHTF + jj;
            act = (bx2 > bx1) && (by2 > by1);
        }
        unsigned vmask = __ballot_sync(0xFFFFFFFFu, valid);
        unsigned amask = __ballot_sync(0xFFFFFFFFu, act);
        if (vmask) {
            int leader = __ffs(vmask) - 1;
            int base = 0;
            if (lane == leader) {
                base = atomicAdd(&g_cnt, __popc(vmask));
                if (amask) atomicAdd(&g_acnt, __popc(amask));
            }
            base = __shfl_sync(0xFFFFFFFFu, base, leader);
            if (valid) {
                int k = base + __popc(vmask & ((1u << lane) - 1u));
                g_cscore[k] = s;
                g_cbox[k]   = make_float4(bx1, by1, bx2, by2);
                g_corig[k]  = c;
                g_cact[k]   = act ? 1 : 0;
            }
        }
    }

    // ---------------- B1: full barrier (everyone needs M) --------------------
    __syncthreads();
    if (tid == 0) {
        __threadfence();
        atomicAdd(&g_bar, 1);
        while (*(volatile int*)&g_bar < NBLK) { }
    }
    __syncthreads();
    __threadfence();

    const int M = *(volatile int*)&g_cnt;
    const int A = *(volatile int*)&g_acnt;

    // ---------------- P1: rank (global + active) via packed u64 keys ---------
    // key = (score_bits << 32) | ~orig: order-isomorphic, unique, nonzero for
    // real entries. Padding key 0 never wins a compare.
    {
        u64*      skey  = (u64*)dyn_smem;                    // [M rounded to 32]
        unsigned* sactw = (unsigned*)(dyn_smem + 73728);     // [ceil(M/32)]

        const int nit = (M + 31) >> 5;
        const int M32 = nit << 5;

        // merged fill: key + act ballot in one pass (warp-uniform trips)
        for (int t = 0; t < M32; t += NTHR) {
            int i = t + tid;
            bool in = (i < M);
            u64 key = in
                ? (((u64)__float_as_uint(g_cscore[i]) << 32)
                   | (u64)(0xFFFFFFFFu - (unsigned)g_corig[i]))
                : 0ull;
            bool a = in && (g_cact[i] != 0);
            unsigned bal = __ballot_sync(0xFFFFFFFFu, a);
            if (i < M32) {
                skey[i] = key;
                if (lane == 0) sactw[i >> 5] = bal;
            }
        }
        __syncthreads();

        // dual-key per warp: share each skey[j] load between two keys;
        // pack (r, ra) as (r<<16)|ra -> one reduction per key.
        for (int kk = bid * 32 + wid; kk < M; kk += 2 * NWARP) {
            const int kA = kk;
            const int kB = kk + NWARP;
            const bool hasB = (kB < M);
            u64 keyA = skey[kA];
            u64 keyB = hasB ? skey[kB] : ~0ull;   // nothing exceeds ~0ull
            int accA = 0, accB = 0;
            for (int it = 0; it < nit; it++) {
                u64 kj = skey[(it << 5) + lane];
                int w  = 0x10000 | (int)((sactw[it] >> lane) & 1u);
                if (kj > keyA) accA += w;
                if (kj > keyB) accB += w;
            }
            accA = __reduce_add_sync(0xFFFFFFFFu, accA);
            accB = __reduce_add_sync(0xFFFFFFFFu, accB);
            if (lane == 0) {
                {
                    int r = accA >> 16, ra = accA & 0xFFFF;
                    float4 bk = g_cbox[kA];
                    g_sbox[r]   = bk;
                    g_sscore[r] = g_cscore[kA];
                    if ((sactw[kA >> 5] >> (kA & 31)) & 1u) {
                        g_abox[ra] = bk; g_amap[ra] = r;
                    }
                }
                if (hasB) {
                    int r = accB >> 16, ra = accB & 0xFFFF;
                    float4 bk = g_cbox[kB];
                    g_sbox[r]   = bk;
                    g_sscore[r] = g_cscore[kB];
                    if ((sactw[kB >> 5] >> (kB & 31)) & 1u) {
                        g_abox[ra] = bk; g_amap[ra] = r;
                    }
                }
            }
        }
    }

    // ---------------- arrive-only checkpoint (no spin for bid != 0) ----------
    __syncthreads();
    if (tid == 0) {
        __threadfence();
        atomicAdd(&g_bar, 1);
    }
    if (bid != 0) return;               // done - block 0 handles the tail

    // block 0: wait for all P1 arrivals (target: NBLK from B1 + NBLK here)
    if (tid == 0) {
        while (*(volatile int*)&g_bar < 2 * NBLK) { }
    }
    __syncthreads();
    __threadfence();

    // ---------------- P4 (block 0): in-SMEM matrix + scan + scatter ----------
    {
        __shared__ u64 skeepA[MAXNW];
        __shared__ u64 skeepR[MAXNW];
        __shared__ u64 snz[MAXNW];

        const int na = (A + 63) >> 6;
        // SMEM layout: sabox [0,16A) | samap [16A,20A) | ssup [align8(20A),..)
        float4* sabox = (float4*)dyn_smem;
        int*    samap = (int*)(dyn_smem + (size_t)A * 16);
        size_t  supoff = ((size_t)A * 20 + 7) & ~(size_t)7;
        u64*    ssup  = (u64*)(dyn_smem + supoff);
        const bool fast = (supoff + (size_t)A * na * 8) <= DSMEM_BYTES;

        for (int a = tid; a < A; a += NTHR) {
            sabox[a] = g_abox[a];
            samap[a] = g_amap[a];
        }
        if (tid < MAXNW) {
            snz[tid] = 0ull;
            if (tid < na) {
                int nb = A - (tid << 6);
                skeepA[tid] = (nb >= 64) ? ~0ull : ((1ull << nb) - 1ull);
            }
            int nwR = (M + 63) >> 6;
            if (tid < nwR) {
                int nb = M - (tid << 6);
                skeepR[tid] = (nb >= 64) ? ~0ull : ((1ull << nb) - 1ull);
            }
        }
        __syncthreads();

        // suppression bit-matrix via warp ballots; division-free predicate:
        // denom = ai+aj-inter+1e-9 > 0 => iou > 0.5 <=> inter > 0.5*denom.
        for (int i = wid; i < A; i += 32) {
            float4 bi = sabox[i];
            float  ai = (bi.z - bi.x) * (bi.w - bi.y);
            u64 rowor = 0;
            for (int w = (i >> 6); w < na; w++) {
                int j1 = (w << 6) + lane;
                int j2 = j1 + 32;
                bool p1 = false, p2 = false;
                if (j1 > i && j1 < A) {
                    float4 bj = sabox[j1];
                    float  aj = (bj.z - bj.x) * (bj.w - bj.y);
                    float iw = fmaxf(fminf(bi.z, bj.z) - fmaxf(bi.x, bj.x), 0.0f);
                    float ih = fmaxf(fminf(bi.w, bj.w) - fmaxf(bi.y, bj.y), 0.0f);
                    float inter = iw * ih;
                    p1 = inter > 0.5f * (ai + aj - inter + 1e-9f);
                }
                if (j2 > i && j2 < A) {
                    float4 bj = sabox[j2];
                    float  aj = (bj.z - bj.x) * (bj.w - bj.y);
                    float iw = fmaxf(fminf(bi.z, bj.z) - fmaxf(bi.x, bj.x), 0.0f);
                    float ih = fmaxf(fminf(bi.w, bj.w) - fmaxf(bi.y, bj.y), 0.0f);
                    float inter = iw * ih;
                    p2 = inter > 0.5f * (ai + aj - inter + 1e-9f);
                }
                unsigned lo = __ballot_sync(0xFFFFFFFFu, p1);
                unsigned hi = __ballot_sync(0xFFFFFFFFu, p2);
                u64 bits = (u64)lo | ((u64)hi << 32);
                if (lane == 0) {
                    if (fast) ssup[(size_t)i * na + w] = bits;
                    else      g_sup[(size_t)i * na + w] = bits;
                }
                rowor |= bits;
            }
            if (lane == 0 && rowor)
                atomicOr(&snz[i >> 6], 1ull << (i & 63));
        }
        __syncthreads();

        // sparse chunked greedy scan over actives
        if (tid < 32 && A > 0) {
            const int ln = tid;
            for (int c = 0; c < na; c++) {
                const int base = c << 6;

                if (ln == 0) {
                    u64 kw  = skeepA[c];
                    u64 rem = kw & snz[c];
                    while (rem) {
                        int b = __ffsll((long long)rem) - 1;
                        u64 s = fast ? ssup[(size_t)(base + b) * na + c]
                                     : g_sup[(size_t)(base + b) * na + c];
                        kw  &= ~s;          // bits in s are strictly > b
                        rem &= ~s;
                        rem &= rem - 1;     // clear processed (lowest) bit
                    }
                    skeepA[c] = kw;
                }
                __syncwarp();

                const u64 kwnz = skeepA[c] & snz[c];
                if (kwnz) {
                    for (int w = c + 1 + ln; w < na; w += 32) {
                        u64 acc = 0, t = kwnz;
                        while (t) {
                            int b = __ffsll((long long)t) - 1;
                            t &= t - 1;
                            acc |= fast ? ssup[(size_t)(base + b) * na + w]
                                        : g_sup[(size_t)(base + b) * na + w];
                        }
                        skeepA[w] &= ~acc;
                    }
                }
                __syncwarp();
            }
        }
        __syncthreads();

        // map suppressed actives back to global sorted ranks
        for (int a = tid; a < A; a += NTHR) {
            if (!((skeepA[a >> 6] >> (a & 63)) & 1ull)) {
                int r = samap[a];
                atomicAnd(&skeepR[r >> 6], ~(1ull << (r & 63)));
            }
        }
        __syncthreads();

        // scatter kept rows (output zeroed in P0)
        for (int r = tid; r < M; r += NTHR) {
            if ((skeepR[r >> 6] >> (r & 63)) & 1ull) {
                float4 b = g_sbox[r];
                out[r * 5 + 0] = g_sscore[r];
                out[r * 5 + 1] = b.x;
                out[r * 5 + 2] = b.y;
                out[r * 5 + 3] = b.z - b.x;
                out[r * 5 + 4] = b.w - b.y;
            }
        }
    }

    // ---------------- final: block 0 is provably last; reset counters --------
    __syncthreads();
    if (tid == 0) {
        g_cnt  = 0;
        g_acnt = 0;
        g_bar  = 0;
        __threadfence();
    }
}

// ---------------------------------------------------------------------------
extern "C" void kernel_launch(void* const* d_in, const int* in_sizes, int n_in,
                              void* d_out, int out_size)
{
    (void)in_sizes; (void)n_in; (void)out_size;
    const float* x   = (const float*)d_in[0];
    float*       out = (float*)d_out;

    cudaFuncSetAttribute(rbb_fused,
                         cudaFuncAttributeMaxDynamicSharedMemorySize,
                         DSMEM_BYTES);

    rbb_fused<<<NBLK, NTHR, DSMEM_BYTES>>>(x, out);
}